// round 6
// baseline (speedup 1.0000x reference)
#include <cuda_runtime.h>

#define NN   100000
#define NE   1600000
#define INF_ 128
#define OUTF 64

#define TILE_M 64
#define KC     32
#define XSS    36
#define RBLK   ((NN + TILE_M - 1) / TILE_M)      // 1563 resid tiles
#define SBLK   ((NE * 16 + 255) / 256)           // 100000 scatter blocks
#define ILV    65                                // interleave period
#define TBLK   (RBLK + SBLK)

__device__ float g_support[(size_t)NN * OUTF];
__device__ float g_resid[(size_t)NN * OUTF];

// ---------------------------------------------------------------------------
// Shared GEMM tile core: 256 threads, 64 nodes, 64 features, K=128.
// tx = tid&15 -> features tx*4..tx*4+3 ; ty = tid>>4 -> nodes ty*4..ty*4+3.
// Wc[k][f] staged in smem by caller-specific code; x staged in KC=32 chunks.
// Inner loop blocked by 4 k's: x via LDS.128 (broadcast), W via LDS.128.
// ---------------------------------------------------------------------------
struct GemmSmem {
  float Wc[128 * 64];       // 32 KB
  float xs[TILE_M * XSS];   // 9.2 KB
};

__device__ __forceinline__ void gemm_core(
    const GemmSmem* s, const float* __restrict__ x, int n0, int tid,
    float acc[4][4]) {
  const int tx = tid & 15;
  const int ty = tid >> 4;
  const float* xrow = s->xs + (ty * 4) * XSS;

  for (int k0 = 0; k0 < INF_; k0 += KC) {
    __syncthreads();
#pragma unroll
    for (int rep = 0; rep < 2; rep++) {
      int i = tid + rep * 256;
      int node = i >> 3, kq = i & 7;
      int gn = n0 + node;
      float4 v = make_float4(0.f, 0.f, 0.f, 0.f);
      if (gn < NN) v = *(const float4*)(x + (size_t)gn * INF_ + k0 + kq * 4);
      *(float4*)((float*)s->xs + node * XSS + kq * 4) = v;
    }
    __syncthreads();

    const float* Wk = s->Wc + k0 * 64 + tx * 4;
#pragma unroll
    for (int kb = 0; kb < KC / 4; kb++) {
      float4 xv0 = *(const float4*)(xrow + 0 * XSS + kb * 4);
      float4 xv1 = *(const float4*)(xrow + 1 * XSS + kb * 4);
      float4 xv2 = *(const float4*)(xrow + 2 * XSS + kb * 4);
      float4 xv3 = *(const float4*)(xrow + 3 * XSS + kb * 4);
#pragma unroll
      for (int j = 0; j < 4; j++) {
        float4 wq = *(const float4*)(Wk + (kb * 4 + j) * 64);
        float xa = (&xv0.x)[j], xb = (&xv1.x)[j];
        float xc = (&xv2.x)[j], xd = (&xv3.x)[j];
        acc[0][0] = fmaf(xa, wq.x, acc[0][0]);
        acc[0][1] = fmaf(xa, wq.y, acc[0][1]);
        acc[0][2] = fmaf(xa, wq.z, acc[0][2]);
        acc[0][3] = fmaf(xa, wq.w, acc[0][3]);
        acc[1][0] = fmaf(xb, wq.x, acc[1][0]);
        acc[1][1] = fmaf(xb, wq.y, acc[1][1]);
        acc[1][2] = fmaf(xb, wq.z, acc[1][2]);
        acc[1][3] = fmaf(xb, wq.w, acc[1][3]);
        acc[2][0] = fmaf(xc, wq.x, acc[2][0]);
        acc[2][1] = fmaf(xc, wq.y, acc[2][1]);
        acc[2][2] = fmaf(xc, wq.z, acc[2][2]);
        acc[2][3] = fmaf(xc, wq.w, acc[2][3]);
        acc[3][0] = fmaf(xd, wq.x, acc[3][0]);
        acc[3][1] = fmaf(xd, wq.y, acc[3][1]);
        acc[3][2] = fmaf(xd, wq.z, acc[3][2]);
        acc[3][3] = fmaf(xd, wq.w, acc[3][3]);
      }
    }
  }
}

// ---------------------------------------------------------------------------
// Kernel 1: support GEMM.  g_support[n,f] = sum_k x[n,k] * weight[k,f]
// ---------------------------------------------------------------------------
__global__ void __launch_bounds__(256) support_gemm(
    const float* __restrict__ x, const float* __restrict__ weight) {
  __shared__ GemmSmem s;
  const int tid = threadIdx.x;
  const int n0 = blockIdx.x * TILE_M;

  for (int i = tid; i < 128 * 64; i += 256) s.Wc[i] = weight[i];  // [k][f]

  float acc[4][4] = {};
  gemm_core(&s, x, n0, tid, acc);

  const int tx = tid & 15, ty = tid >> 4;
  const int f = tx * 4;
#pragma unroll
  for (int i = 0; i < 4; i++) {
    int gn = n0 + ty * 4 + i;
    if (gn < NN)
      *(float4*)(g_support + (size_t)gn * OUTF + f) =
          make_float4(acc[i][0], acc[i][1], acc[i][2], acc[i][3]);
  }
}

// ---------------------------------------------------------------------------
// Kernel 2 (fused): residual GEMM tiles interleaved with edge scatter.
//   every ILV-th block: g_resid[n,o] = sum_k x[n,k]*res_w[o,k] + res_b[o]
//   all other blocks:   16 lanes/edge, red.global.add.v4.f32 into out
// ---------------------------------------------------------------------------
__global__ void __launch_bounds__(256) fused_resid_scatter(
    const float* __restrict__ x, const float* __restrict__ res_w,
    const float* __restrict__ res_b,
    const int* __restrict__ src, const int* __restrict__ dst,
    const float* __restrict__ ew, float* __restrict__ out) {
  __shared__ GemmSmem s;
  const unsigned b = blockIdx.x;
  const unsigned r = b / ILV, m = b % ILV;
  const int tid = threadIdx.x;

  if (m == 0 && r < RBLK) {
    // ---- residual GEMM tile r ----
    const int n0 = (int)r * TILE_M;
    for (int i = tid; i < 64 * 128; i += 256) {
      int o = i >> 7, k = i & 127;
      s.Wc[k * 64 + o] = res_w[i];          // res_w [64,128] row-major
    }
    float acc[4][4] = {};
    gemm_core(&s, x, n0, tid, acc);

    const int tx = tid & 15, ty = tid >> 4;
    const int f = tx * 4;
    float4 rb = *(const float4*)(res_b + f);
#pragma unroll
    for (int i = 0; i < 4; i++) {
      int gn = n0 + ty * 4 + i;
      if (gn < NN)
        *(float4*)(g_resid + (size_t)gn * OUTF + f) =
            make_float4(acc[i][0] + rb.x, acc[i][1] + rb.y,
                        acc[i][2] + rb.z, acc[i][3] + rb.w);
    }
    return;
  }

  // ---- scatter block ----
  unsigned nres = r + (m ? 1u : 0u);
  if (nres > RBLK) nres = RBLK;
  unsigned sbk = b - nres;                  // scatter block index 0..SBLK-1
  unsigned t = sbk * 256u + tid;
  unsigned e = t >> 4;
  unsigned q = t & 15;
  if (e >= NE) return;
  int sn = __ldg(src + e);
  int dn = __ldg(dst + e);
  float w = __ldg(ew + e);
  float4 v = __ldg((const float4*)(g_support + (size_t)sn * OUTF) + q);
  v.x *= w; v.y *= w; v.z *= w; v.w *= w;
  float* p = out + (size_t)dn * OUTF + q * 4;
  asm volatile("red.global.add.v4.f32 [%0], {%1, %2, %3, %4};"
               :: "l"(p), "f"(v.x), "f"(v.y), "f"(v.z), "f"(v.w)
               : "memory");
}

// ---------------------------------------------------------------------------
// Kernel 3: finalize. 16 lanes/node: +bias, LayerNorm(64), ReLU, +resid.
// ---------------------------------------------------------------------------
__global__ void __launch_bounds__(256) finalize_kernel(
    float* __restrict__ out, const float* __restrict__ bias,
    const float* __restrict__ gamma, const float* __restrict__ beta) {
  unsigned t = blockIdx.x * 256u + threadIdx.x;
  unsigned n = t >> 4;
  unsigned q = t & 15;
  if (n >= NN) return;

  float4 v = *(float4*)(out + (size_t)n * OUTF + q * 4);
  float4 b = *(const float4*)(bias + q * 4);
  v.x += b.x; v.y += b.y; v.z += b.z; v.w += b.w;

  float s  = v.x + v.y + v.z + v.w;
  float s2 = v.x * v.x + v.y * v.y + v.z * v.z + v.w * v.w;
#pragma unroll
  for (int mm = 8; mm >= 1; mm >>= 1) {
    s  += __shfl_xor_sync(0xffffffffu, s, mm);
    s2 += __shfl_xor_sync(0xffffffffu, s2, mm);
  }
  float mu  = s * (1.f / 64.f);
  float var = s2 * (1.f / 64.f) - mu * mu;
  float inv = rsqrtf(var + 1e-5f);

  float4 g  = *(const float4*)(gamma + q * 4);
  float4 be = *(const float4*)(beta + q * 4);
  float4 rr = *(const float4*)(g_resid + (size_t)n * OUTF + q * 4);

  v.x = fmaxf((v.x - mu) * inv * g.x + be.x, 0.f) + rr.x;
  v.y = fmaxf((v.y - mu) * inv * g.y + be.y, 0.f) + rr.y;
  v.z = fmaxf((v.z - mu) * inv * g.z + be.z, 0.f) + rr.z;
  v.w = fmaxf((v.w - mu) * inv * g.w + be.w, 0.f) + rr.w;

  *(float4*)(out + (size_t)n * OUTF + q * 4) = v;
}

// ---------------------------------------------------------------------------
extern "C" void kernel_launch(void* const* d_in, const int* in_sizes, int n_in,
                              void* d_out, int out_size) {
  const float* x      = (const float*)d_in[0];
  const float* weight = (const float*)d_in[1];
  const float* bias   = (const float*)d_in[2];
  const float* gamma  = (const float*)d_in[3];
  const float* beta   = (const float*)d_in[4];
  const float* res_w  = (const float*)d_in[5];
  const float* res_b  = (const float*)d_in[6];
  const float* ew     = (const float*)d_in[7];
  const int*   esrc   = (const int*)d_in[8];
  const int*   edst   = (const int*)d_in[9];
  float* out = (float*)d_out;

  cudaMemsetAsync(d_out, 0, (size_t)NN * OUTF * sizeof(float), 0);

  support_gemm<<<RBLK, 256>>>(x, weight);

  fused_resid_scatter<<<TBLK, 256>>>(x, res_w, res_b, esrc, edst, ew, out);

  unsigned fblocks = (unsigned)(((long long)NN * 16 + 255) / 256);
  finalize_kernel<<<fblocks, 256>>>(out, bias, gamma, beta);
}

// round 7
// speedup vs baseline: 1.9184x; 1.9184x over previous
#include <cuda_runtime.h>
#include <cuda_bf16.h>
#include <mma.h>
using namespace nvcuda;

#define NN   100000
#define NNP  100032   // padded to 64-node tiles: 1563*64
#define NE   1600000
#define INF_ 128
#define OUTF 64
#define TILE_M 64
#define NBLK ((NN + TILE_M - 1) / TILE_M)   // 1563

__device__ float g_support[(size_t)NNP * OUTF];
__device__ float g_resid[(size_t)NNP * OUTF];
// Combined weights split to bf16 hi/lo, row-major [k][f] (f: 0-63 weight, 64-127 res_w^T)
__device__ __align__(16) __nv_bfloat16 g_whi[128 * 128];
__device__ __align__(16) __nv_bfloat16 g_wlo[128 * 128];

// ---------------------------------------------------------------------------
// Prep: split combined weight matrix into bf16 hi/lo.
// ---------------------------------------------------------------------------
__global__ void prep_weights(const float* __restrict__ w,
                             const float* __restrict__ rw) {
  int i = blockIdx.x * blockDim.x + threadIdx.x;
  if (i >= 128 * 128) return;
  int k = i >> 7, f = i & 127;
  float v = (f < 64) ? w[k * 64 + f] : rw[(f - 64) * 128 + k];
  __nv_bfloat16 h = __float2bfloat16(v);
  g_whi[i] = h;
  g_wlo[i] = __float2bfloat16(v - __bfloat162float(h));
}

// ---------------------------------------------------------------------------
// Kernel 1: WMMA split-bf16 combined GEMM.
//   D[n, 0:64]   -> g_support = x @ weight
//   D[n, 64:128] -> g_resid   = x @ res_w^T      (res_b added in finalize)
// 256 threads = 8 warps (2 node-tiles x 4 feature-tiles), 64 nodes/block.
// Each warp: 2x2 fragments of 16x16, K=128 in 8 steps, 3 passes (hh, hl, lh).
// ---------------------------------------------------------------------------
#define LDX 136
#define LDW 136
#define SM_XHI 0
#define SM_XLO (64 * LDX)
#define SM_WHI (2 * 64 * LDX)
#define SM_WLO (2 * 64 * LDX + 128 * LDW)
#define GEMM_SMEM ((2 * 64 * LDX + 2 * 128 * LDW) * 2)   // 104448 B

__global__ void __launch_bounds__(256) gemm_kernel(const float* __restrict__ x) {
  extern __shared__ __nv_bfloat16 sm[];
  __nv_bfloat16* xhi = sm + SM_XHI;
  __nv_bfloat16* xlo = sm + SM_XLO;
  __nv_bfloat16* whi = sm + SM_WHI;
  __nv_bfloat16* wlo = sm + SM_WLO;
  const int tid = threadIdx.x;
  const int n0 = blockIdx.x * TILE_M;

  // Stage pre-split weights (uint4 = 8 bf16)
  {
    const uint4* sh = (const uint4*)g_whi;
    const uint4* sl = (const uint4*)g_wlo;
#pragma unroll
    for (int rep = 0; rep < 8; rep++) {
      int i = tid + rep * 256;               // 2048 uint4
      int r = i >> 4, c = i & 15;
      *(uint4*)(whi + r * LDW + c * 8) = sh[i];
      *(uint4*)(wlo + r * LDW + c * 8) = sl[i];
    }
  }
  // Stage x, split hi/lo on the fly
#pragma unroll
  for (int rep = 0; rep < 8; rep++) {
    int i = tid + rep * 256;                 // 2048 float4
    int node = i >> 5, c = i & 31;
    int gn = n0 + node;
    if (gn >= NN) gn = NN - 1;
    float4 v = *(const float4*)(x + (size_t)gn * INF_ + c * 4);
    __nv_bfloat16 h0 = __float2bfloat16(v.x), h1 = __float2bfloat16(v.y);
    __nv_bfloat16 h2 = __float2bfloat16(v.z), h3 = __float2bfloat16(v.w);
    __nv_bfloat16 l0 = __float2bfloat16(v.x - __bfloat162float(h0));
    __nv_bfloat16 l1 = __float2bfloat16(v.y - __bfloat162float(h1));
    __nv_bfloat16 l2 = __float2bfloat16(v.z - __bfloat162float(h2));
    __nv_bfloat16 l3 = __float2bfloat16(v.w - __bfloat162float(h3));
    __nv_bfloat162* ph = (__nv_bfloat162*)(xhi + node * LDX + c * 4);
    __nv_bfloat162* pl = (__nv_bfloat162*)(xlo + node * LDX + c * 4);
    ph[0] = __nv_bfloat162(h0, h1); ph[1] = __nv_bfloat162(h2, h3);
    pl[0] = __nv_bfloat162(l0, l1); pl[1] = __nv_bfloat162(l2, l3);
  }
  __syncthreads();

  const int w = tid >> 5;
  const int wm = w & 1;        // node 32-tile
  const int wn = w >> 1;       // feature 32-tile (0..3)

  wmma::fragment<wmma::accumulator, 16, 16, 16, float> acc[2][2];
#pragma unroll
  for (int i = 0; i < 2; i++)
#pragma unroll
    for (int j = 0; j < 2; j++) wmma::fill_fragment(acc[i][j], 0.f);

#pragma unroll
  for (int k = 0; k < 128; k += 16) {
    wmma::fragment<wmma::matrix_a, 16, 16, 16, __nv_bfloat16, wmma::row_major> ahi[2], alo[2];
    wmma::fragment<wmma::matrix_b, 16, 16, 16, __nv_bfloat16, wmma::row_major> bhi[2], blo[2];
#pragma unroll
    for (int i = 0; i < 2; i++) {
      wmma::load_matrix_sync(ahi[i], xhi + (wm * 32 + i * 16) * LDX + k, LDX);
      wmma::load_matrix_sync(alo[i], xlo + (wm * 32 + i * 16) * LDX + k, LDX);
    }
#pragma unroll
    for (int j = 0; j < 2; j++) {
      wmma::load_matrix_sync(bhi[j], whi + k * LDW + wn * 32 + j * 16, LDW);
      wmma::load_matrix_sync(blo[j], wlo + k * LDW + wn * 32 + j * 16, LDW);
    }
#pragma unroll
    for (int i = 0; i < 2; i++)
#pragma unroll
      for (int j = 0; j < 2; j++) {
        wmma::mma_sync(acc[i][j], ahi[i], bhi[j], acc[i][j]);
        wmma::mma_sync(acc[i][j], ahi[i], blo[j], acc[i][j]);
        wmma::mma_sync(acc[i][j], alo[i], bhi[j], acc[i][j]);
      }
  }

#pragma unroll
  for (int i = 0; i < 2; i++)
#pragma unroll
    for (int j = 0; j < 2; j++) {
      int row = n0 + wm * 32 + i * 16;       // < NNP always (padded)
      int col = wn * 32 + j * 16;
      float* dst = (col < 64)
                       ? (g_support + (size_t)row * OUTF + col)
                       : (g_resid + (size_t)row * OUTF + (col - 64));
      wmma::store_matrix_sync(dst, acc[i][j], OUTF, wmma::mem_row_major);
    }
}

// ---------------------------------------------------------------------------
// Kernel 2: edge scatter. 16 threads/edge, one float4 each, red.global.add.v4.
// ---------------------------------------------------------------------------
__global__ void __launch_bounds__(256) scatter_kernel(
    const int* __restrict__ src, const int* __restrict__ dst,
    const float* __restrict__ ew, float* __restrict__ out) {
  unsigned t = blockIdx.x * 256u + threadIdx.x;
  unsigned e = t >> 4;
  unsigned q = t & 15;
  if (e >= NE) return;
  int s = __ldg(src + e);
  int d = __ldg(dst + e);
  float w = __ldg(ew + e);
  float4 v = __ldg((const float4*)(g_support + (size_t)s * OUTF) + q);
  v.x *= w; v.y *= w; v.z *= w; v.w *= w;
  float* p = out + (size_t)d * OUTF + q * 4;
  asm volatile("red.global.add.v4.f32 [%0], {%1, %2, %3, %4};"
               :: "l"(p), "f"(v.x), "f"(v.y), "f"(v.z), "f"(v.w)
               : "memory");
}

// ---------------------------------------------------------------------------
// Kernel 3: finalize. 16 lanes/node: +bias, LayerNorm(64), ReLU, +resid+res_b.
// ---------------------------------------------------------------------------
__global__ void __launch_bounds__(256) finalize_kernel(
    float* __restrict__ out, const float* __restrict__ bias,
    const float* __restrict__ gamma, const float* __restrict__ beta,
    const float* __restrict__ res_b) {
  unsigned t = blockIdx.x * 256u + threadIdx.x;
  unsigned n = t >> 4;
  unsigned q = t & 15;
  if (n >= NN) return;

  float4 v = *(float4*)(out + (size_t)n * OUTF + q * 4);
  float4 b = *(const float4*)(bias + q * 4);
  v.x += b.x; v.y += b.y; v.z += b.z; v.w += b.w;

  float s  = v.x + v.y + v.z + v.w;
  float s2 = v.x * v.x + v.y * v.y + v.z * v.z + v.w * v.w;
#pragma unroll
  for (int m = 8; m >= 1; m >>= 1) {
    s  += __shfl_xor_sync(0xffffffffu, s, m);
    s2 += __shfl_xor_sync(0xffffffffu, s2, m);
  }
  float mu  = s * (1.f / 64.f);
  float var = s2 * (1.f / 64.f) - mu * mu;
  float inv = rsqrtf(var + 1e-5f);

  float4 g  = *(const float4*)(gamma + q * 4);
  float4 be = *(const float4*)(beta + q * 4);
  float4 r  = *(const float4*)(g_resid + (size_t)n * OUTF + q * 4);
  float4 rb = *(const float4*)(res_b + q * 4);

  v.x = fmaxf((v.x - mu) * inv * g.x + be.x, 0.f) + r.x + rb.x;
  v.y = fmaxf((v.y - mu) * inv * g.y + be.y, 0.f) + r.y + rb.y;
  v.z = fmaxf((v.z - mu) * inv * g.z + be.z, 0.f) + r.z + rb.z;
  v.w = fmaxf((v.w - mu) * inv * g.w + be.w, 0.f) + r.w + rb.w;

  *(float4*)(out + (size_t)n * OUTF + q * 4) = v;
}

// ---------------------------------------------------------------------------
extern "C" void kernel_launch(void* const* d_in, const int* in_sizes, int n_in,
                              void* d_out, int out_size) {
  const float* x      = (const float*)d_in[0];
  const float* weight = (const float*)d_in[1];
  const float* bias   = (const float*)d_in[2];
  const float* gamma  = (const float*)d_in[3];
  const float* beta   = (const float*)d_in[4];
  const float* res_w  = (const float*)d_in[5];
  const float* res_b  = (const float*)d_in[6];
  const float* ew     = (const float*)d_in[7];
  const int*   esrc   = (const int*)d_in[8];
  const int*   edst   = (const int*)d_in[9];
  float* out = (float*)d_out;

  cudaFuncSetAttribute(gemm_kernel,
                       cudaFuncAttributeMaxDynamicSharedMemorySize, GEMM_SMEM);

  cudaMemsetAsync(d_out, 0, (size_t)NN * OUTF * sizeof(float), 0);

  prep_weights<<<64, 256>>>(weight, res_w);
  gemm_kernel<<<NBLK, 256, GEMM_SMEM>>>(x);

  unsigned sblocks = (unsigned)(((long long)NE * 16 + 255) / 256);
  scatter_kernel<<<sblocks, 256>>>(esrc, edst, ew, out);

  unsigned fblocks = (unsigned)(((long long)NN * 16 + 255) / 256);
  finalize_kernel<<<fblocks, 256>>>(out, bias, gamma, beta, res_b);
}

// round 8
// speedup vs baseline: 2.2761x; 1.1865x over previous
#include <cuda_runtime.h>
#include <cuda_bf16.h>
#include <mma.h>
using namespace nvcuda;

#define NN   100000
#define NNP  100032
#define NE   1600000
#define INF_ 128
#define OUTF 64
#define TILE_M 64
#define NBLK ((NN + TILE_M - 1) / TILE_M)   // 1563
#define CAP  64
#define MAX_OVF 65536

__device__ float g_support[(size_t)NNP * OUTF];
__device__ float g_resid[(size_t)NNP * OUTF];
__device__ __align__(16) __nv_bfloat16 g_whi[128 * 128];
__device__ __align__(16) __nv_bfloat16 g_wlo[128 * 128];
__device__ int  g_cnt[NNP];
__device__ int  g_ovf_cnt;
__device__ int  g_ovf[MAX_OVF];
__device__ int2 g_ell[(size_t)NNP * CAP];   // {src, float_bits(w)}

// ---------------------------------------------------------------------------
// Prep: split combined weight matrix into bf16 hi/lo. [k][f], f>=64 -> res_w^T
// ---------------------------------------------------------------------------
__global__ void prep_weights(const float* __restrict__ w,
                             const float* __restrict__ rw) {
  int i = blockIdx.x * blockDim.x + threadIdx.x;
  if (i >= 128 * 128) return;
  int k = i >> 7, f = i & 127;
  float v = (f < 64) ? w[k * 64 + f] : rw[(f - 64) * 128 + k];
  __nv_bfloat16 h = __float2bfloat16(v);
  g_whi[i] = h;
  g_wlo[i] = __float2bfloat16(v - __bfloat162float(h));
}

// ---------------------------------------------------------------------------
// Kernel 1: WMMA split-bf16 combined GEMM (support | resid), 64 nodes/block.
// ---------------------------------------------------------------------------
#define LDX 136
#define LDW 136
#define SM_XHI 0
#define SM_XLO (64 * LDX)
#define SM_WHI (2 * 64 * LDX)
#define SM_WLO (2 * 64 * LDX + 128 * LDW)
#define GEMM_SMEM ((2 * 64 * LDX + 2 * 128 * LDW) * 2)

__global__ void __launch_bounds__(256) gemm_kernel(const float* __restrict__ x) {
  extern __shared__ __nv_bfloat16 sm[];
  __nv_bfloat16* xhi = sm + SM_XHI;
  __nv_bfloat16* xlo = sm + SM_XLO;
  __nv_bfloat16* whi = sm + SM_WHI;
  __nv_bfloat16* wlo = sm + SM_WLO;
  const int tid = threadIdx.x;
  const int n0 = blockIdx.x * TILE_M;

  {
    const uint4* sh = (const uint4*)g_whi;
    const uint4* sl = (const uint4*)g_wlo;
#pragma unroll
    for (int rep = 0; rep < 8; rep++) {
      int i = tid + rep * 256;
      int r = i >> 4, c = i & 15;
      *(uint4*)(whi + r * LDW + c * 8) = sh[i];
      *(uint4*)(wlo + r * LDW + c * 8) = sl[i];
    }
  }
#pragma unroll
  for (int rep = 0; rep < 8; rep++) {
    int i = tid + rep * 256;
    int node = i >> 5, c = i & 31;
    int gn = n0 + node;
    if (gn >= NN) gn = NN - 1;
    float4 v = *(const float4*)(x + (size_t)gn * INF_ + c * 4);
    __nv_bfloat16 h0 = __float2bfloat16(v.x), h1 = __float2bfloat16(v.y);
    __nv_bfloat16 h2 = __float2bfloat16(v.z), h3 = __float2bfloat16(v.w);
    __nv_bfloat16 l0 = __float2bfloat16(v.x - __bfloat162float(h0));
    __nv_bfloat16 l1 = __float2bfloat16(v.y - __bfloat162float(h1));
    __nv_bfloat16 l2 = __float2bfloat16(v.z - __bfloat162float(h2));
    __nv_bfloat16 l3 = __float2bfloat16(v.w - __bfloat162float(h3));
    __nv_bfloat162* ph = (__nv_bfloat162*)(xhi + node * LDX + c * 4);
    __nv_bfloat162* pl = (__nv_bfloat162*)(xlo + node * LDX + c * 4);
    ph[0] = __nv_bfloat162(h0, h1); ph[1] = __nv_bfloat162(h2, h3);
    pl[0] = __nv_bfloat162(l0, l1); pl[1] = __nv_bfloat162(l2, l3);
  }
  __syncthreads();

  const int w = tid >> 5;
  const int wm = w & 1;
  const int wn = w >> 1;

  wmma::fragment<wmma::accumulator, 16, 16, 16, float> acc[2][2];
#pragma unroll
  for (int i = 0; i < 2; i++)
#pragma unroll
    for (int j = 0; j < 2; j++) wmma::fill_fragment(acc[i][j], 0.f);

#pragma unroll
  for (int k = 0; k < 128; k += 16) {
    wmma::fragment<wmma::matrix_a, 16, 16, 16, __nv_bfloat16, wmma::row_major> ahi[2], alo[2];
    wmma::fragment<wmma::matrix_b, 16, 16, 16, __nv_bfloat16, wmma::row_major> bhi[2], blo[2];
#pragma unroll
    for (int i = 0; i < 2; i++) {
      wmma::load_matrix_sync(ahi[i], xhi + (wm * 32 + i * 16) * LDX + k, LDX);
      wmma::load_matrix_sync(alo[i], xlo + (wm * 32 + i * 16) * LDX + k, LDX);
    }
#pragma unroll
    for (int j = 0; j < 2; j++) {
      wmma::load_matrix_sync(bhi[j], whi + k * LDW + wn * 32 + j * 16, LDW);
      wmma::load_matrix_sync(blo[j], wlo + k * LDW + wn * 32 + j * 16, LDW);
    }
#pragma unroll
    for (int i = 0; i < 2; i++)
#pragma unroll
      for (int j = 0; j < 2; j++) {
        wmma::mma_sync(acc[i][j], ahi[i], bhi[j], acc[i][j]);
        wmma::mma_sync(acc[i][j], ahi[i], blo[j], acc[i][j]);
        wmma::mma_sync(acc[i][j], alo[i], bhi[j], acc[i][j]);
      }
  }

#pragma unroll
  for (int i = 0; i < 2; i++)
#pragma unroll
    for (int j = 0; j < 2; j++) {
      int row = n0 + wm * 32 + i * 16;
      int col = wn * 32 + j * 16;
      float* dst = (col < 64)
                       ? (g_support + (size_t)row * OUTF + col)
                       : (g_resid + (size_t)row * OUTF + (col - 64));
      wmma::store_matrix_sync(dst, acc[i][j], OUTF, wmma::mem_row_major);
    }
}

// ---------------------------------------------------------------------------
// Kernel 2: ELL placement. 1 thread/edge.
// ---------------------------------------------------------------------------
__global__ void __launch_bounds__(256) placement_kernel(
    const int* __restrict__ src, const int* __restrict__ dst,
    const float* __restrict__ ew) {
  unsigned e = blockIdx.x * 256u + threadIdx.x;
  if (e >= NE) return;
  int d = __ldg(dst + e);
  int pos = atomicAdd(&g_cnt[d], 1);
  if (pos < CAP) {
    g_ell[(size_t)d * CAP + pos] = make_int2(__ldg(src + e),
                                             __float_as_int(__ldg(ew + e)));
  } else {
    int o = atomicAdd(&g_ovf_cnt, 1);
    if (o < MAX_OVF) g_ovf[o] = (int)e;
  }
}

// ---------------------------------------------------------------------------
// Kernel 2b: overflow edges (normally zero) -> atomic add into out.
// ---------------------------------------------------------------------------
__global__ void overflow_kernel(const int* __restrict__ src,
                                const int* __restrict__ dst,
                                const float* __restrict__ ew,
                                float* __restrict__ out) {
  int m = g_ovf_cnt;
  if (m > MAX_OVF) m = MAX_OVF;
  for (int i = threadIdx.x; i < m; i += 256) {
    int e = g_ovf[i];
    int s = src[e], d = dst[e];
    float w = ew[e];
    for (int f = 0; f < OUTF; f++)
      atomicAdd(&out[(size_t)d * OUTF + f], w * g_support[(size_t)s * OUTF + f]);
  }
}

// ---------------------------------------------------------------------------
// Kernel 3: fused gather + finalize. 16 lanes/node (2 nodes per warp).
// acc = out-row (overflow staging, usually 0) + sum_e w_e * support[src_e]
// then +bias, LN(64), ReLU, +resid+res_b, write out.
// ---------------------------------------------------------------------------
__global__ void __launch_bounds__(256) gather_finalize(
    float* __restrict__ out, const float* __restrict__ bias,
    const float* __restrict__ gamma, const float* __restrict__ beta,
    const float* __restrict__ res_b) {
  unsigned t = blockIdx.x * 256u + threadIdx.x;
  unsigned n = t >> 4;
  unsigned q = t & 15;            // lane group position
  const unsigned gmask = 0xffffu << (threadIdx.x & 16);

  int deg = g_cnt[n];
  if (deg > CAP) deg = CAP;

  float4 acc = *(const float4*)(out + (size_t)n * OUTF + q * 4);
  const int2* ellrow = g_ell + (size_t)n * CAP;

  for (int base = 0; base < deg; base += 16) {
    int2 mine = make_int2(0, 0);
    if (base + (int)q < deg) mine = __ldg(ellrow + base + q);
    int c16 = deg - base;
    if (c16 > 16) c16 = 16;
    int j = 0;
    for (; j + 2 <= c16; j += 2) {
      int sx0 = __shfl_sync(gmask, mine.x, j, 16);
      int sw0 = __shfl_sync(gmask, mine.y, j, 16);
      int sx1 = __shfl_sync(gmask, mine.x, j + 1, 16);
      int sw1 = __shfl_sync(gmask, mine.y, j + 1, 16);
      float4 v0 = __ldg((const float4*)(g_support + (size_t)sx0 * OUTF) + q);
      float4 v1 = __ldg((const float4*)(g_support + (size_t)sx1 * OUTF) + q);
      float w0 = __int_as_float(sw0), w1 = __int_as_float(sw1);
      acc.x = fmaf(w0, v0.x, acc.x); acc.y = fmaf(w0, v0.y, acc.y);
      acc.z = fmaf(w0, v0.z, acc.z); acc.w = fmaf(w0, v0.w, acc.w);
      acc.x = fmaf(w1, v1.x, acc.x); acc.y = fmaf(w1, v1.y, acc.y);
      acc.z = fmaf(w1, v1.z, acc.z); acc.w = fmaf(w1, v1.w, acc.w);
    }
    if (j < c16) {
      int sx0 = __shfl_sync(gmask, mine.x, j, 16);
      int sw0 = __shfl_sync(gmask, mine.y, j, 16);
      float4 v0 = __ldg((const float4*)(g_support + (size_t)sx0 * OUTF) + q);
      float w0 = __int_as_float(sw0);
      acc.x = fmaf(w0, v0.x, acc.x); acc.y = fmaf(w0, v0.y, acc.y);
      acc.z = fmaf(w0, v0.z, acc.z); acc.w = fmaf(w0, v0.w, acc.w);
    }
  }

  // finalize
  float4 b = *(const float4*)(bias + q * 4);
  acc.x += b.x; acc.y += b.y; acc.z += b.z; acc.w += b.w;

  float s  = acc.x + acc.y + acc.z + acc.w;
  float s2 = acc.x * acc.x + acc.y * acc.y + acc.z * acc.z + acc.w * acc.w;
#pragma unroll
  for (int m = 8; m >= 1; m >>= 1) {
    s  += __shfl_xor_sync(gmask, s, m, 16);
    s2 += __shfl_xor_sync(gmask, s2, m, 16);
  }
  float mu  = s * (1.f / 64.f);
  float var = s2 * (1.f / 64.f) - mu * mu;
  float inv = rsqrtf(var + 1e-5f);

  float4 g  = *(const float4*)(gamma + q * 4);
  float4 be = *(const float4*)(beta + q * 4);
  float4 r  = *(const float4*)(g_resid + (size_t)n * OUTF + q * 4);
  float4 rb = *(const float4*)(res_b + q * 4);

  acc.x = fmaxf((acc.x - mu) * inv * g.x + be.x, 0.f) + r.x + rb.x;
  acc.y = fmaxf((acc.y - mu) * inv * g.y + be.y, 0.f) + r.y + rb.y;
  acc.z = fmaxf((acc.z - mu) * inv * g.z + be.z, 0.f) + r.z + rb.z;
  acc.w = fmaxf((acc.w - mu) * inv * g.w + be.w, 0.f) + r.w + rb.w;

  *(float4*)(out + (size_t)n * OUTF + q * 4) = acc;
}

// ---------------------------------------------------------------------------
extern "C" void kernel_launch(void* const* d_in, const int* in_sizes, int n_in,
                              void* d_out, int out_size) {
  const float* x      = (const float*)d_in[0];
  const float* weight = (const float*)d_in[1];
  const float* bias   = (const float*)d_in[2];
  const float* gamma  = (const float*)d_in[3];
  const float* beta   = (const float*)d_in[4];
  const float* res_w  = (const float*)d_in[5];
  const float* res_b  = (const float*)d_in[6];
  const float* ew     = (const float*)d_in[7];
  const int*   esrc   = (const int*)d_in[8];
  const int*   edst   = (const int*)d_in[9];
  float* out = (float*)d_out;

  cudaFuncSetAttribute(gemm_kernel,
                       cudaFuncAttributeMaxDynamicSharedMemorySize, GEMM_SMEM);

  void* cntp = nullptr; void* ovfp = nullptr;
  cudaGetSymbolAddress(&cntp, g_cnt);
  cudaGetSymbolAddress(&ovfp, g_ovf_cnt);

  cudaMemsetAsync(d_out, 0, (size_t)NN * OUTF * sizeof(float), 0);
  cudaMemsetAsync(cntp, 0, NNP * sizeof(int), 0);
  cudaMemsetAsync(ovfp, 0, sizeof(int), 0);

  prep_weights<<<64, 256>>>(weight, res_w);
  gemm_kernel<<<NBLK, 256, GEMM_SMEM>>>(x);

  placement_kernel<<<(NE + 255) / 256, 256>>>(esrc, edst, ew);
  overflow_kernel<<<1, 256>>>(esrc, edst, ew, out);

  gather_finalize<<<(NN * 16) / 256, 256>>>(out, bias, gamma, beta, res_b);
}

// round 9
// speedup vs baseline: 2.3250x; 1.0215x over previous
#include <cuda_runtime.h>
#include <cuda_bf16.h>
#include <mma.h>
using namespace nvcuda;

#define NN   100000
#define NNP  100032
#define NE   1600000
#define INF_ 128
#define OUTF 64
#define TILE_M 64
#define NBLK ((NN + TILE_M - 1) / TILE_M)   // 1563
#define CAP  64

__device__ float g_support[(size_t)NNP * OUTF];
__device__ float g_resid[(size_t)NNP * OUTF];
__device__ __align__(16) __nv_bfloat16 g_whi[128 * 128];
__device__ __align__(16) __nv_bfloat16 g_wlo[128 * 128];
__device__ int  g_cnt[NNP + 1];             // [NNP] = overflow counter (unused path)
__device__ int2 g_ell[(size_t)NNP * CAP];   // {src, float_bits(w)}

// ---------------------------------------------------------------------------
// Prep: split combined weight matrix into bf16 hi/lo. [k][f], f>=64 -> res_w^T
// ---------------------------------------------------------------------------
__global__ void prep_weights(const float* __restrict__ w,
                             const float* __restrict__ rw) {
  int i = blockIdx.x * blockDim.x + threadIdx.x;
  if (i >= 128 * 128) return;
  int k = i >> 7, f = i & 127;
  float v = (f < 64) ? w[k * 64 + f] : rw[(f - 64) * 128 + k];
  __nv_bfloat16 h = __float2bfloat16(v);
  g_whi[i] = h;
  g_wlo[i] = __float2bfloat16(v - __bfloat162float(h));
}

// ---------------------------------------------------------------------------
// Kernel 1: WMMA split-bf16 combined GEMM (support | resid), 64 nodes/block.
// ---------------------------------------------------------------------------
#define LDX 136
#define LDW 136
#define SM_XHI 0
#define SM_XLO (64 * LDX)
#define SM_WHI (2 * 64 * LDX)
#define SM_WLO (2 * 64 * LDX + 128 * LDW)
#define GEMM_SMEM ((2 * 64 * LDX + 2 * 128 * LDW) * 2)

__global__ void __launch_bounds__(256) gemm_kernel(const float* __restrict__ x) {
  extern __shared__ __nv_bfloat16 sm[];
  __nv_bfloat16* xhi = sm + SM_XHI;
  __nv_bfloat16* xlo = sm + SM_XLO;
  __nv_bfloat16* whi = sm + SM_WHI;
  __nv_bfloat16* wlo = sm + SM_WLO;
  const int tid = threadIdx.x;
  const int n0 = blockIdx.x * TILE_M;

  {
    const uint4* sh = (const uint4*)g_whi;
    const uint4* sl = (const uint4*)g_wlo;
#pragma unroll
    for (int rep = 0; rep < 8; rep++) {
      int i = tid + rep * 256;
      int r = i >> 4, c = i & 15;
      *(uint4*)(whi + r * LDW + c * 8) = sh[i];
      *(uint4*)(wlo + r * LDW + c * 8) = sl[i];
    }
  }
#pragma unroll
  for (int rep = 0; rep < 8; rep++) {
    int i = tid + rep * 256;
    int node = i >> 5, c = i & 31;
    int gn = n0 + node;
    if (gn >= NN) gn = NN - 1;
    float4 v = *(const float4*)(x + (size_t)gn * INF_ + c * 4);
    __nv_bfloat16 h0 = __float2bfloat16(v.x), h1 = __float2bfloat16(v.y);
    __nv_bfloat16 h2 = __float2bfloat16(v.z), h3 = __float2bfloat16(v.w);
    __nv_bfloat16 l0 = __float2bfloat16(v.x - __bfloat162float(h0));
    __nv_bfloat16 l1 = __float2bfloat16(v.y - __bfloat162float(h1));
    __nv_bfloat16 l2 = __float2bfloat16(v.z - __bfloat162float(h2));
    __nv_bfloat16 l3 = __float2bfloat16(v.w - __bfloat162float(h3));
    __nv_bfloat162* ph = (__nv_bfloat162*)(xhi + node * LDX + c * 4);
    __nv_bfloat162* pl = (__nv_bfloat162*)(xlo + node * LDX + c * 4);
    ph[0] = __nv_bfloat162(h0, h1); ph[1] = __nv_bfloat162(h2, h3);
    pl[0] = __nv_bfloat162(l0, l1); pl[1] = __nv_bfloat162(l2, l3);
  }
  __syncthreads();

  const int w = tid >> 5;
  const int wm = w & 1;
  const int wn = w >> 1;

  wmma::fragment<wmma::accumulator, 16, 16, 16, float> acc[2][2];
#pragma unroll
  for (int i = 0; i < 2; i++)
#pragma unroll
    for (int j = 0; j < 2; j++) wmma::fill_fragment(acc[i][j], 0.f);

#pragma unroll
  for (int k = 0; k < 128; k += 16) {
    wmma::fragment<wmma::matrix_a, 16, 16, 16, __nv_bfloat16, wmma::row_major> ahi[2], alo[2];
    wmma::fragment<wmma::matrix_b, 16, 16, 16, __nv_bfloat16, wmma::row_major> bhi[2], blo[2];
#pragma unroll
    for (int i = 0; i < 2; i++) {
      wmma::load_matrix_sync(ahi[i], xhi + (wm * 32 + i * 16) * LDX + k, LDX);
      wmma::load_matrix_sync(alo[i], xlo + (wm * 32 + i * 16) * LDX + k, LDX);
    }
#pragma unroll
    for (int j = 0; j < 2; j++) {
      wmma::load_matrix_sync(bhi[j], whi + k * LDW + wn * 32 + j * 16, LDW);
      wmma::load_matrix_sync(blo[j], wlo + k * LDW + wn * 32 + j * 16, LDW);
    }
#pragma unroll
    for (int i = 0; i < 2; i++)
#pragma unroll
      for (int j = 0; j < 2; j++) {
        wmma::mma_sync(acc[i][j], ahi[i], bhi[j], acc[i][j]);
        wmma::mma_sync(acc[i][j], ahi[i], blo[j], acc[i][j]);
        wmma::mma_sync(acc[i][j], alo[i], bhi[j], acc[i][j]);
      }
  }

#pragma unroll
  for (int i = 0; i < 2; i++)
#pragma unroll
    for (int j = 0; j < 2; j++) {
      int row = n0 + wm * 32 + i * 16;
      int col = wn * 32 + j * 16;
      float* dst = (col < 64)
                       ? (g_support + (size_t)row * OUTF + col)
                       : (g_resid + (size_t)row * OUTF + (col - 64));
      wmma::store_matrix_sync(dst, acc[i][j], OUTF, wmma::mem_row_major);
    }
}

// ---------------------------------------------------------------------------
// Kernel 2: ELL placement. 1 thread/edge. Overflow (never hit with CAP=64,
// Poisson(16) degrees) handled inline with scalar atomics into out.
// ---------------------------------------------------------------------------
__global__ void __launch_bounds__(256) placement_kernel(
    const int* __restrict__ src, const int* __restrict__ dst,
    const float* __restrict__ ew, float* __restrict__ out) {
  unsigned e = blockIdx.x * 256u + threadIdx.x;
  if (e >= NE) return;
  int d = __ldg(dst + e);
  int pos = atomicAdd(&g_cnt[d], 1);
  if (pos < CAP) {
    g_ell[(size_t)d * CAP + pos] = make_int2(__ldg(src + e),
                                             __float_as_int(__ldg(ew + e)));
  } else {
    int s = __ldg(src + e);
    float w = __ldg(ew + e);
    for (int f = 0; f < OUTF; f++)
      atomicAdd(&out[(size_t)d * OUTF + f], w * g_support[(size_t)s * OUTF + f]);
  }
}

// ---------------------------------------------------------------------------
// Kernel 3: fused gather + finalize. 16 lanes/node (2 nodes per warp).
// MLP=4 gathers per step. acc starts from out-row (overflow staging, ~always 0).
// ---------------------------------------------------------------------------
__global__ void __launch_bounds__(256) gather_finalize(
    float* __restrict__ out, const float* __restrict__ bias,
    const float* __restrict__ gamma, const float* __restrict__ beta,
    const float* __restrict__ res_b) {
  unsigned t = blockIdx.x * 256u + threadIdx.x;
  unsigned n = t >> 4;
  unsigned q = t & 15;
  const unsigned gmask = 0xffffu << (threadIdx.x & 16);

  int deg = g_cnt[n];
  if (deg > CAP) deg = CAP;

  float4 acc = *(const float4*)(out + (size_t)n * OUTF + q * 4);
  const int2* ellrow = g_ell + (size_t)n * CAP;

  for (int base = 0; base < deg; base += 16) {
    int2 mine = make_int2(0, 0);
    if (base + (int)q < deg) mine = __ldg(ellrow + base + q);
    int c16 = deg - base;
    if (c16 > 16) c16 = 16;
    int j = 0;
    for (; j + 4 <= c16; j += 4) {
      int sx0 = __shfl_sync(gmask, mine.x, j + 0, 16);
      int sw0 = __shfl_sync(gmask, mine.y, j + 0, 16);
      int sx1 = __shfl_sync(gmask, mine.x, j + 1, 16);
      int sw1 = __shfl_sync(gmask, mine.y, j + 1, 16);
      int sx2 = __shfl_sync(gmask, mine.x, j + 2, 16);
      int sw2 = __shfl_sync(gmask, mine.y, j + 2, 16);
      int sx3 = __shfl_sync(gmask, mine.x, j + 3, 16);
      int sw3 = __shfl_sync(gmask, mine.y, j + 3, 16);
      float4 v0 = __ldg((const float4*)(g_support + (size_t)sx0 * OUTF) + q);
      float4 v1 = __ldg((const float4*)(g_support + (size_t)sx1 * OUTF) + q);
      float4 v2 = __ldg((const float4*)(g_support + (size_t)sx2 * OUTF) + q);
      float4 v3 = __ldg((const float4*)(g_support + (size_t)sx3 * OUTF) + q);
      float w0 = __int_as_float(sw0), w1 = __int_as_float(sw1);
      float w2 = __int_as_float(sw2), w3 = __int_as_float(sw3);
      acc.x = fmaf(w0, v0.x, acc.x); acc.y = fmaf(w0, v0.y, acc.y);
      acc.z = fmaf(w0, v0.z, acc.z); acc.w = fmaf(w0, v0.w, acc.w);
      acc.x = fmaf(w1, v1.x, acc.x); acc.y = fmaf(w1, v1.y, acc.y);
      acc.z = fmaf(w1, v1.z, acc.z); acc.w = fmaf(w1, v1.w, acc.w);
      acc.x = fmaf(w2, v2.x, acc.x); acc.y = fmaf(w2, v2.y, acc.y);
      acc.z = fmaf(w2, v2.z, acc.z); acc.w = fmaf(w2, v2.w, acc.w);
      acc.x = fmaf(w3, v3.x, acc.x); acc.y = fmaf(w3, v3.y, acc.y);
      acc.z = fmaf(w3, v3.z, acc.z); acc.w = fmaf(w3, v3.w, acc.w);
    }
    for (; j < c16; j++) {
      int sx0 = __shfl_sync(gmask, mine.x, j, 16);
      int sw0 = __shfl_sync(gmask, mine.y, j, 16);
      float4 v0 = __ldg((const float4*)(g_support + (size_t)sx0 * OUTF) + q);
      float w0 = __int_as_float(sw0);
      acc.x = fmaf(w0, v0.x, acc.x); acc.y = fmaf(w0, v0.y, acc.y);
      acc.z = fmaf(w0, v0.z, acc.z); acc.w = fmaf(w0, v0.w, acc.w);
    }
  }

  // finalize
  float4 b = *(const float4*)(bias + q * 4);
  acc.x += b.x; acc.y += b.y; acc.z += b.z; acc.w += b.w;

  float s  = acc.x + acc.y + acc.z + acc.w;
  float s2 = acc.x * acc.x + acc.y * acc.y + acc.z * acc.z + acc.w * acc.w;
#pragma unroll
  for (int m = 8; m >= 1; m >>= 1) {
    s  += __shfl_xor_sync(gmask, s, m, 16);
    s2 += __shfl_xor_sync(gmask, s2, m, 16);
  }
  float mu  = s * (1.f / 64.f);
  float var = s2 * (1.f / 64.f) - mu * mu;
  float inv = rsqrtf(var + 1e-5f);

  float4 g  = *(const float4*)(gamma + q * 4);
  float4 be = *(const float4*)(beta + q * 4);
  float4 r  = *(const float4*)(g_resid + (size_t)n * OUTF + q * 4);
  float4 rb = *(const float4*)(res_b + q * 4);

  acc.x = fmaxf((acc.x - mu) * inv * g.x + be.x, 0.f) + r.x + rb.x;
  acc.y = fmaxf((acc.y - mu) * inv * g.y + be.y, 0.f) + r.y + rb.y;
  acc.z = fmaxf((acc.z - mu) * inv * g.z + be.z, 0.f) + r.z + rb.z;
  acc.w = fmaxf((acc.w - mu) * inv * g.w + be.w, 0.f) + r.w + rb.w;

  *(float4*)(out + (size_t)n * OUTF + q * 4) = acc;
}

// ---------------------------------------------------------------------------
extern "C" void kernel_launch(void* const* d_in, const int* in_sizes, int n_in,
                              void* d_out, int out_size) {
  const float* x      = (const float*)d_in[0];
  const float* weight = (const float*)d_in[1];
  const float* bias   = (const float*)d_in[2];
  const float* gamma  = (const float*)d_in[3];
  const float* beta   = (const float*)d_in[4];
  const float* res_w  = (const float*)d_in[5];
  const float* res_b  = (const float*)d_in[6];
  const float* ew     = (const float*)d_in[7];
  const int*   esrc   = (const int*)d_in[8];
  const int*   edst   = (const int*)d_in[9];
  float* out = (float*)d_out;

  cudaFuncSetAttribute(gemm_kernel,
                       cudaFuncAttributeMaxDynamicSharedMemorySize, GEMM_SMEM);

  void* cntp = nullptr;
  cudaGetSymbolAddress(&cntp, g_cnt);

  cudaMemsetAsync(d_out, 0, (size_t)NN * OUTF * sizeof(float), 0);
  cudaMemsetAsync(cntp, 0, (NNP + 1) * sizeof(int), 0);

  prep_weights<<<64, 256>>>(weight, res_w);
  gemm_kernel<<<NBLK, 256, GEMM_SMEM>>>(x);

  placement_kernel<<<(NE + 255) / 256, 256>>>(esrc, edst, ew, out);

  gather_finalize<<<(NN * 16) / 256, 256>>>(out, bias, gamma, beta, res_b);
}

// round 10
// speedup vs baseline: 2.4026x; 1.0333x over previous
#include <cuda_runtime.h>
#include <cuda_bf16.h>
#include <mma.h>
using namespace nvcuda;

#define NN   100000
#define NNP  100032
#define NE   1600000
#define INF_ 128
#define OUTF 64
#define TILE_M 64
#define NBLK ((NN + TILE_M - 1) / TILE_M)   // 1563
#define CAP  64

__device__ float g_support[(size_t)NNP * OUTF];
__device__ float g_resid[(size_t)NNP * OUTF];
__device__ __align__(16) __nv_bfloat16 g_whi[128 * 128];
__device__ __align__(16) __nv_bfloat16 g_wlo[128 * 128];
__device__ int  g_cnt[NNP];
__device__ int2 g_ell[(size_t)NNP * CAP];   // {src, float_bits(w)}

// ---------------------------------------------------------------------------
// Prep: split combined weight matrix into bf16 hi/lo. [k][f], f>=64 -> res_w^T
// ---------------------------------------------------------------------------
__global__ void prep_weights(const float* __restrict__ w,
                             const float* __restrict__ rw) {
  int i = blockIdx.x * blockDim.x + threadIdx.x;
  if (i >= 128 * 128) return;
  int k = i >> 7, f = i & 127;
  float v = (f < 64) ? w[k * 64 + f] : rw[(f - 64) * 128 + k];
  __nv_bfloat16 h = __float2bfloat16(v);
  g_whi[i] = h;
  g_wlo[i] = __float2bfloat16(v - __bfloat162float(h));
}

// ---------------------------------------------------------------------------
// Kernel 1: WMMA split-bf16 combined GEMM (support | resid), 64 nodes/block.
// ---------------------------------------------------------------------------
#define LDX 136
#define LDW 136
#define SM_XHI 0
#define SM_XLO (64 * LDX)
#define SM_WHI (2 * 64 * LDX)
#define SM_WLO (2 * 64 * LDX + 128 * LDW)
#define GEMM_SMEM ((2 * 64 * LDX + 2 * 128 * LDW) * 2)

__global__ void __launch_bounds__(256) gemm_kernel(const float* __restrict__ x) {
  extern __shared__ __nv_bfloat16 sm[];
  __nv_bfloat16* xhi = sm + SM_XHI;
  __nv_bfloat16* xlo = sm + SM_XLO;
  __nv_bfloat16* whi = sm + SM_WHI;
  __nv_bfloat16* wlo = sm + SM_WLO;
  const int tid = threadIdx.x;
  const int n0 = blockIdx.x * TILE_M;

  {
    const uint4* sh = (const uint4*)g_whi;
    const uint4* sl = (const uint4*)g_wlo;
#pragma unroll
    for (int rep = 0; rep < 8; rep++) {
      int i = tid + rep * 256;
      int r = i >> 4, c = i & 15;
      *(uint4*)(whi + r * LDW + c * 8) = sh[i];
      *(uint4*)(wlo + r * LDW + c * 8) = sl[i];
    }
  }
#pragma unroll
  for (int rep = 0; rep < 8; rep++) {
    int i = tid + rep * 256;
    int node = i >> 5, c = i & 31;
    int gn = n0 + node;
    if (gn >= NN) gn = NN - 1;
    float4 v = *(const float4*)(x + (size_t)gn * INF_ + c * 4);
    __nv_bfloat16 h0 = __float2bfloat16(v.x), h1 = __float2bfloat16(v.y);
    __nv_bfloat16 h2 = __float2bfloat16(v.z), h3 = __float2bfloat16(v.w);
    __nv_bfloat16 l0 = __float2bfloat16(v.x - __bfloat162float(h0));
    __nv_bfloat16 l1 = __float2bfloat16(v.y - __bfloat162float(h1));
    __nv_bfloat16 l2 = __float2bfloat16(v.z - __bfloat162float(h2));
    __nv_bfloat16 l3 = __float2bfloat16(v.w - __bfloat162float(h3));
    __nv_bfloat162* ph = (__nv_bfloat162*)(xhi + node * LDX + c * 4);
    __nv_bfloat162* pl = (__nv_bfloat162*)(xlo + node * LDX + c * 4);
    ph[0] = __nv_bfloat162(h0, h1); ph[1] = __nv_bfloat162(h2, h3);
    pl[0] = __nv_bfloat162(l0, l1); pl[1] = __nv_bfloat162(l2, l3);
  }
  __syncthreads();

  const int w = tid >> 5;
  const int wm = w & 1;
  const int wn = w >> 1;

  wmma::fragment<wmma::accumulator, 16, 16, 16, float> acc[2][2];
#pragma unroll
  for (int i = 0; i < 2; i++)
#pragma unroll
    for (int j = 0; j < 2; j++) wmma::fill_fragment(acc[i][j], 0.f);

#pragma unroll
  for (int k = 0; k < 128; k += 16) {
    wmma::fragment<wmma::matrix_a, 16, 16, 16, __nv_bfloat16, wmma::row_major> ahi[2], alo[2];
    wmma::fragment<wmma::matrix_b, 16, 16, 16, __nv_bfloat16, wmma::row_major> bhi[2], blo[2];
#pragma unroll
    for (int i = 0; i < 2; i++) {
      wmma::load_matrix_sync(ahi[i], xhi + (wm * 32 + i * 16) * LDX + k, LDX);
      wmma::load_matrix_sync(alo[i], xlo + (wm * 32 + i * 16) * LDX + k, LDX);
    }
#pragma unroll
    for (int j = 0; j < 2; j++) {
      wmma::load_matrix_sync(bhi[j], whi + k * LDW + wn * 32 + j * 16, LDW);
      wmma::load_matrix_sync(blo[j], wlo + k * LDW + wn * 32 + j * 16, LDW);
    }
#pragma unroll
    for (int i = 0; i < 2; i++)
#pragma unroll
      for (int j = 0; j < 2; j++) {
        wmma::mma_sync(acc[i][j], ahi[i], bhi[j], acc[i][j]);
        wmma::mma_sync(acc[i][j], ahi[i], blo[j], acc[i][j]);
        wmma::mma_sync(acc[i][j], alo[i], bhi[j], acc[i][j]);
      }
  }

#pragma unroll
  for (int i = 0; i < 2; i++)
#pragma unroll
    for (int j = 0; j < 2; j++) {
      int row = n0 + wm * 32 + i * 16;
      int col = wn * 32 + j * 16;
      float* dst = (col < 64)
                       ? (g_support + (size_t)row * OUTF + col)
                       : (g_resid + (size_t)row * OUTF + (col - 64));
      wmma::store_matrix_sync(dst, acc[i][j], OUTF, wmma::mem_row_major);
    }
}

// ---------------------------------------------------------------------------
// Kernel 2: ELL placement. 1 thread/edge. Overflow (never hit with CAP=64,
// Poisson(16) degrees) handled inline with scalar atomics into out.
// ---------------------------------------------------------------------------
__global__ void __launch_bounds__(256) placement_kernel(
    const int* __restrict__ src, const int* __restrict__ dst,
    const float* __restrict__ ew, float* __restrict__ out) {
  unsigned e = blockIdx.x * 256u + threadIdx.x;
  if (e >= NE) return;
  int d = __ldg(dst + e);
  int s = __ldg(src + e);
  float w = __ldg(ew + e);
  int pos = atomicAdd(&g_cnt[d], 1);
  if (pos < CAP) {
    g_ell[(size_t)d * CAP + pos] = make_int2(s, __float_as_int(w));
  } else {
    for (int f = 0; f < OUTF; f++)
      atomicAdd(&out[(size_t)d * OUTF + f], w * g_support[(size_t)s * OUTF + f]);
  }
}

// ---------------------------------------------------------------------------
// Kernel 3: fused gather + finalize. 16 lanes/node (2 nodes per warp).
// ELL entries read via broadcast LDG (no shfl). 8 independent gathers in
// flight (MLP=8). acc starts at 0; out-row is read only on overflow nodes.
// ---------------------------------------------------------------------------
__global__ void __launch_bounds__(256) gather_finalize(
    float* __restrict__ out, const float* __restrict__ bias,
    const float* __restrict__ gamma, const float* __restrict__ beta,
    const float* __restrict__ res_b) {
  unsigned t = blockIdx.x * 256u + threadIdx.x;
  unsigned n = t >> 4;
  unsigned q = t & 15;
  const unsigned gmask = 0xffffu << (threadIdx.x & 16);

  int deg_raw = g_cnt[n];
  int deg = deg_raw > CAP ? CAP : deg_raw;

  float4 acc;
  if (deg_raw > CAP)            // overflow staged in out (essentially never)
    acc = *(const float4*)(out + (size_t)n * OUTF + q * 4);
  else
    acc = make_float4(0.f, 0.f, 0.f, 0.f);

  const int2* ellrow = g_ell + (size_t)n * CAP;

  for (int base = 0; base < deg; base += 8) {
    int2 e[8];
#pragma unroll
    for (int u = 0; u < 8; u++) {
      int idx = base + u;
      e[u] = (idx < deg) ? __ldg(ellrow + idx) : make_int2(0, 0);
    }
    float4 v[8];
#pragma unroll
    for (int u = 0; u < 8; u++)
      v[u] = __ldg((const float4*)(g_support + (size_t)e[u].x * OUTF) + q);
#pragma unroll
    for (int u = 0; u < 8; u++) {
      float w = __int_as_float(e[u].y);
      acc.x = fmaf(w, v[u].x, acc.x);
      acc.y = fmaf(w, v[u].y, acc.y);
      acc.z = fmaf(w, v[u].z, acc.z);
      acc.w = fmaf(w, v[u].w, acc.w);
    }
  }

  // finalize
  float4 b = *(const float4*)(bias + q * 4);
  acc.x += b.x; acc.y += b.y; acc.z += b.z; acc.w += b.w;

  float s  = acc.x + acc.y + acc.z + acc.w;
  float s2 = acc.x * acc.x + acc.y * acc.y + acc.z * acc.z + acc.w * acc.w;
#pragma unroll
  for (int m = 8; m >= 1; m >>= 1) {
    s  += __shfl_xor_sync(gmask, s, m, 16);
    s2 += __shfl_xor_sync(gmask, s2, m, 16);
  }
  float mu  = s * (1.f / 64.f);
  float var = s2 * (1.f / 64.f) - mu * mu;
  float inv = rsqrtf(var + 1e-5f);

  float4 g  = *(const float4*)(gamma + q * 4);
  float4 be = *(const float4*)(beta + q * 4);
  float4 r  = *(const float4*)(g_resid + (size_t)n * OUTF + q * 4);
  float4 rb = *(const float4*)(res_b + q * 4);

  acc.x = fmaxf((acc.x - mu) * inv * g.x + be.x, 0.f) + r.x + rb.x;
  acc.y = fmaxf((acc.y - mu) * inv * g.y + be.y, 0.f) + r.y + rb.y;
  acc.z = fmaxf((acc.z - mu) * inv * g.z + be.z, 0.f) + r.z + rb.z;
  acc.w = fmaxf((acc.w - mu) * inv * g.w + be.w, 0.f) + r.w + rb.w;

  *(float4*)(out + (size_t)n * OUTF + q * 4) = acc;
}

// ---------------------------------------------------------------------------
extern "C" void kernel_launch(void* const* d_in, const int* in_sizes, int n_in,
                              void* d_out, int out_size) {
  const float* x      = (const float*)d_in[0];
  const float* weight = (const float*)d_in[1];
  const float* bias   = (const float*)d_in[2];
  const float* gamma  = (const float*)d_in[3];
  const float* beta   = (const float*)d_in[4];
  const float* res_w  = (const float*)d_in[5];
  const float* res_b  = (const float*)d_in[6];
  const float* ew     = (const float*)d_in[7];
  const int*   esrc   = (const int*)d_in[8];
  const int*   edst   = (const int*)d_in[9];
  float* out = (float*)d_out;

  cudaFuncSetAttribute(gemm_kernel,
                       cudaFuncAttributeMaxDynamicSharedMemorySize, GEMM_SMEM);

  void* cntp = nullptr;
  cudaGetSymbolAddress(&cntp, g_cnt);

  cudaMemsetAsync(d_out, 0, (size_t)NN * OUTF * sizeof(float), 0);
  cudaMemsetAsync(cntp, 0, NNP * sizeof(int), 0);

  prep_weights<<<64, 256>>>(weight, res_w);
  gemm_kernel<<<NBLK, 256, GEMM_SMEM>>>(x);

  placement_kernel<<<(NE + 255) / 256, 256>>>(esrc, edst, ew, out);

  gather_finalize<<<(NN * 16) / 256, 256>>>(out, bias, gamma, beta, res_b);
}

// round 11
// speedup vs baseline: 2.5654x; 1.0678x over previous
#include <cuda_runtime.h>
#include <cuda_bf16.h>
#include <mma.h>
using namespace nvcuda;

#define NN   100000
#define NNP  100096   // padded to 128-node tiles: 782*128
#define NE   1600000
#define INF_ 128
#define OUTF 64
#define TILE_M 128
#define NBLK ((NN + TILE_M - 1) / TILE_M)   // 782
#define CAP  64
#define MAX_OVF 65536

__device__ float g_support[(size_t)NNP * OUTF];
__device__ float g_resid[(size_t)NNP * OUTF];
__device__ __align__(16) __nv_bfloat16 g_whi[128 * 128];
__device__ __align__(16) __nv_bfloat16 g_wlo[128 * 128];
__device__ int  g_cnt[NNP + 1];             // [NNP] = overflow counter
__device__ int  g_ovf[MAX_OVF];
__device__ int2 g_ell[(size_t)NNP * CAP];   // {src*16 (float4 units), w bits}

// ---------------------------------------------------------------------------
// Prep: split combined weight matrix into bf16 hi/lo. [k][f], f>=64 -> res_w^T
// ---------------------------------------------------------------------------
__global__ void prep_weights(const float* __restrict__ w,
                             const float* __restrict__ rw) {
  int i = blockIdx.x * blockDim.x + threadIdx.x;
  if (i >= 128 * 128) return;
  int k = i >> 7, f = i & 127;
  float v = (f < 64) ? w[k * 64 + f] : rw[(f - 64) * 128 + k];
  __nv_bfloat16 h = __float2bfloat16(v);
  g_whi[i] = h;
  g_wlo[i] = __float2bfloat16(v - __bfloat162float(h));
}

// ---------------------------------------------------------------------------
// Kernel 1: WMMA split-bf16 combined GEMM (support | resid).
// 128 nodes/block, 512 threads = 16 warps (4 m-tiles x 4 n-tiles),
// each warp 2x2 fragments of 16x16, 3 passes (hh, hl, lh), K=128.
// ---------------------------------------------------------------------------
#define LDX 136
#define LDW 136
#define SM_XHI 0
#define SM_XLO (128 * LDX)
#define SM_WHI (2 * 128 * LDX)
#define SM_WLO (2 * 128 * LDX + 128 * LDW)
#define GEMM_SMEM ((2 * 128 * LDX + 2 * 128 * LDW) * 2)   // 139264 B

__global__ void __launch_bounds__(512) gemm_kernel(const float* __restrict__ x) {
  extern __shared__ __nv_bfloat16 sm[];
  __nv_bfloat16* xhi = sm + SM_XHI;
  __nv_bfloat16* xlo = sm + SM_XLO;
  __nv_bfloat16* whi = sm + SM_WHI;
  __nv_bfloat16* wlo = sm + SM_WLO;
  const int tid = threadIdx.x;
  const int n0 = blockIdx.x * TILE_M;

  // Stage pre-split weights (2048 uint4 per array)
  {
    const uint4* sh = (const uint4*)g_whi;
    const uint4* sl = (const uint4*)g_wlo;
#pragma unroll
    for (int rep = 0; rep < 4; rep++) {
      int i = tid + rep * 512;
      int r = i >> 4, c = i & 15;
      *(uint4*)(whi + r * LDW + c * 8) = sh[i];
      *(uint4*)(wlo + r * LDW + c * 8) = sl[i];
    }
  }
  // Stage x (128 nodes x 32 float4), split hi/lo on the fly
#pragma unroll
  for (int rep = 0; rep < 8; rep++) {
    int i = tid + rep * 512;                 // 4096 float4
    int node = i >> 5, c = i & 31;
    int gn = n0 + node;
    if (gn >= NN) gn = NN - 1;
    float4 v = *(const float4*)(x + (size_t)gn * INF_ + c * 4);
    __nv_bfloat16 h0 = __float2bfloat16(v.x), h1 = __float2bfloat16(v.y);
    __nv_bfloat16 h2 = __float2bfloat16(v.z), h3 = __float2bfloat16(v.w);
    __nv_bfloat16 l0 = __float2bfloat16(v.x - __bfloat162float(h0));
    __nv_bfloat16 l1 = __float2bfloat16(v.y - __bfloat162float(h1));
    __nv_bfloat16 l2 = __float2bfloat16(v.z - __bfloat162float(h2));
    __nv_bfloat16 l3 = __float2bfloat16(v.w - __bfloat162float(h3));
    __nv_bfloat162* ph = (__nv_bfloat162*)(xhi + node * LDX + c * 4);
    __nv_bfloat162* pl = (__nv_bfloat162*)(xlo + node * LDX + c * 4);
    ph[0] = __nv_bfloat162(h0, h1); ph[1] = __nv_bfloat162(h2, h3);
    pl[0] = __nv_bfloat162(l0, l1); pl[1] = __nv_bfloat162(l2, l3);
  }
  __syncthreads();

  const int wid = tid >> 5;
  const int wm = wid & 3;       // node 32-tile (0..3)
  const int wn = wid >> 2;      // feature 32-tile (0..3)

  wmma::fragment<wmma::accumulator, 16, 16, 16, float> acc[2][2];
#pragma unroll
  for (int i = 0; i < 2; i++)
#pragma unroll
    for (int j = 0; j < 2; j++) wmma::fill_fragment(acc[i][j], 0.f);

#pragma unroll
  for (int k = 0; k < 128; k += 16) {
    wmma::fragment<wmma::matrix_a, 16, 16, 16, __nv_bfloat16, wmma::row_major> ahi[2], alo[2];
    wmma::fragment<wmma::matrix_b, 16, 16, 16, __nv_bfloat16, wmma::row_major> bhi[2], blo[2];
#pragma unroll
    for (int i = 0; i < 2; i++) {
      wmma::load_matrix_sync(ahi[i], xhi + (wm * 32 + i * 16) * LDX + k, LDX);
      wmma::load_matrix_sync(alo[i], xlo + (wm * 32 + i * 16) * LDX + k, LDX);
    }
#pragma unroll
    for (int j = 0; j < 2; j++) {
      wmma::load_matrix_sync(bhi[j], whi + k * LDW + wn * 32 + j * 16, LDW);
      wmma::load_matrix_sync(blo[j], wlo + k * LDW + wn * 32 + j * 16, LDW);
    }
#pragma unroll
    for (int i = 0; i < 2; i++)
#pragma unroll
      for (int j = 0; j < 2; j++) {
        wmma::mma_sync(acc[i][j], ahi[i], bhi[j], acc[i][j]);
        wmma::mma_sync(acc[i][j], ahi[i], blo[j], acc[i][j]);
        wmma::mma_sync(acc[i][j], alo[i], bhi[j], acc[i][j]);
      }
  }

#pragma unroll
  for (int i = 0; i < 2; i++)
#pragma unroll
    for (int j = 0; j < 2; j++) {
      int row = n0 + wm * 32 + i * 16;       // < NNP (padded)
      int col = wn * 32 + j * 16;
      float* dst = (col < 64)
                       ? (g_support + (size_t)row * OUTF + col)
                       : (g_resid + (size_t)row * OUTF + (col - 64));
      wmma::store_matrix_sync(dst, acc[i][j], OUTF, wmma::mem_row_major);
    }
}

// ---------------------------------------------------------------------------
// Kernel 2: ELL placement. 1 thread/edge. src pre-scaled to float4-row units.
// Overflow (never hit: CAP=64 vs Poisson(16) degrees) -> small list.
// ---------------------------------------------------------------------------
__global__ void __launch_bounds__(256) placement_kernel(
    const int* __restrict__ src, const int* __restrict__ dst,
    const float* __restrict__ ew) {
  unsigned e = blockIdx.x * 256u + threadIdx.x;
  if (e >= NE) return;
  int d = __ldg(dst + e);
  int s = __ldg(src + e);
  float w = __ldg(ew + e);
  int pos = atomicAdd(&g_cnt[d], 1);
  if (pos < CAP) {
    g_ell[(size_t)d * CAP + pos] = make_int2(s * (OUTF / 4), __float_as_int(w));
  } else {
    int o = atomicAdd(&g_cnt[NNP], 1);
    if (o < MAX_OVF) g_ovf[o] = (int)e;
  }
}

// ---------------------------------------------------------------------------
// Kernel 3: fused gather + finalize. 16 lanes/node (2 nodes per warp).
// Broadcast-LDG ELL entries, MLP=8 gathers, 32-bit address math.
// Overflow nodes (deg>CAP) additionally scan the tiny g_ovf list.
// ---------------------------------------------------------------------------
__global__ void __launch_bounds__(256) gather_finalize(
    float* __restrict__ out, const float* __restrict__ bias,
    const float* __restrict__ gamma, const float* __restrict__ beta,
    const float* __restrict__ res_b,
    const int* __restrict__ src, const int* __restrict__ dst,
    const float* __restrict__ ew) {
  unsigned t = blockIdx.x * 256u + threadIdx.x;
  unsigned n = t >> 4;
  unsigned q = t & 15;
  const unsigned gmask = 0xffffu << (threadIdx.x & 16);

  int deg_raw = g_cnt[n];
  int deg = deg_raw > CAP ? CAP : deg_raw;

  float4 acc = make_float4(0.f, 0.f, 0.f, 0.f);
  const int2* ellrow = g_ell + (size_t)n * CAP;
  const float4* supf4 = (const float4*)g_support;

  for (int base = 0; base < deg; base += 8) {
    int2 e[8];
#pragma unroll
    for (int u = 0; u < 8; u++) {
      int idx = base + u;
      e[u] = (idx < deg) ? __ldg(ellrow + idx) : make_int2(0, 0);
    }
    float4 v[8];
#pragma unroll
    for (int u = 0; u < 8; u++)
      v[u] = __ldg(supf4 + (unsigned)(e[u].x + q));
#pragma unroll
    for (int u = 0; u < 8; u++) {
      float w = (base + u < deg) ? __int_as_float(e[u].y) : 0.f;
      acc.x = fmaf(w, v[u].x, acc.x);
      acc.y = fmaf(w, v[u].y, acc.y);
      acc.z = fmaf(w, v[u].z, acc.z);
      acc.w = fmaf(w, v[u].w, acc.w);
    }
  }

  if (deg_raw > CAP) {          // essentially never taken
    int m = g_cnt[NNP];
    if (m > MAX_OVF) m = MAX_OVF;
    for (int i = 0; i < m; i++) {
      int e = g_ovf[i];
      if ((unsigned)__ldg(dst + e) == n) {
        float w = __ldg(ew + e);
        float4 v = __ldg(supf4 + (unsigned)(__ldg(src + e) * (OUTF / 4) + q));
        acc.x = fmaf(w, v.x, acc.x); acc.y = fmaf(w, v.y, acc.y);
        acc.z = fmaf(w, v.z, acc.z); acc.w = fmaf(w, v.w, acc.w);
      }
    }
  }

  // finalize
  float4 b = *(const float4*)(bias + q * 4);
  acc.x += b.x; acc.y += b.y; acc.z += b.z; acc.w += b.w;

  float s  = acc.x + acc.y + acc.z + acc.w;
  float s2 = acc.x * acc.x + acc.y * acc.y + acc.z * acc.z + acc.w * acc.w;
#pragma unroll
  for (int m = 8; m >= 1; m >>= 1) {
    s  += __shfl_xor_sync(gmask, s, m, 16);
    s2 += __shfl_xor_sync(gmask, s2, m, 16);
  }
  float mu  = s * (1.f / 64.f);
  float var = s2 * (1.f / 64.f) - mu * mu;
  float inv = rsqrtf(var + 1e-5f);

  float4 g  = *(const float4*)(gamma + q * 4);
  float4 be = *(const float4*)(beta + q * 4);
  float4 r  = *(const float4*)(g_resid + (size_t)n * OUTF + q * 4);
  float4 rb = *(const float4*)(res_b + q * 4);

  acc.x = fmaxf((acc.x - mu) * inv * g.x + be.x, 0.f) + r.x + rb.x;
  acc.y = fmaxf((acc.y - mu) * inv * g.y + be.y, 0.f) + r.y + rb.y;
  acc.z = fmaxf((acc.z - mu) * inv * g.z + be.z, 0.f) + r.z + rb.z;
  acc.w = fmaxf((acc.w - mu) * inv * g.w + be.w, 0.f) + r.w + rb.w;

  *(float4*)(out + (size_t)n * OUTF + q * 4) = acc;
}

// ---------------------------------------------------------------------------
extern "C" void kernel_launch(void* const* d_in, const int* in_sizes, int n_in,
                              void* d_out, int out_size) {
  const float* x      = (const float*)d_in[0];
  const float* weight = (const float*)d_in[1];
  const float* bias   = (const float*)d_in[2];
  const float* gamma  = (const float*)d_in[3];
  const float* beta   = (const float*)d_in[4];
  const float* res_w  = (const float*)d_in[5];
  const float* res_b  = (const float*)d_in[6];
  const float* ew     = (const float*)d_in[7];
  const int*   esrc   = (const int*)d_in[8];
  const int*   edst   = (const int*)d_in[9];
  float* out = (float*)d_out;

  cudaFuncSetAttribute(gemm_kernel,
                       cudaFuncAttributeMaxDynamicSharedMemorySize, GEMM_SMEM);

  void* cntp = nullptr;
  cudaGetSymbolAddress(&cntp, g_cnt);
  cudaMemsetAsync(cntp, 0, (NNP + 1) * sizeof(int), 0);

  prep_weights<<<64, 256>>>(weight, res_w);
  gemm_kernel<<<NBLK, 512, GEMM_SMEM>>>(x);

  placement_kernel<<<(NE + 255) / 256, 256>>>(esrc, edst, ew);

  gather_finalize<<<(NN * 16) / 256, 256>>>(out, bias, gamma, beta, res_b,
                                            esrc, edst, ew);
}